// round 13
// baseline (speedup 1.0000x reference)
#include <cuda_runtime.h>

#define EPSF 1e-5f

// Precomputed categorical results: Y[g][cat][o] = sigmoid(GN(emb[g*100+cat]) @ W_cat[g] + b_cat[g])
__device__ __align__(16) float d_Y[100 * 100 * 128];
// Transposed num weights: WnumT[o][i] = W_num[i][o]  (128 x 100)
__device__ __align__(16) float d_WnumT[128 * 100];
__device__ __align__(16) float d_bnumT[128 * 100];

__device__ __forceinline__ float sigf(float x) { return 1.0f / (1.0f + __expf(-x)); }

__device__ __forceinline__ float sig_tanh(float x) {
    // sigmoid(x) = 0.5*tanh(0.5x) + 0.5 ; MUFU.TANH
    float t;
    asm("tanh.approx.f32 %0, %1;" : "=f"(t) : "f"(0.5f * x));
    return fmaf(0.5f, t, 0.5f);
}

// ---------------- Kernel 1: precompute Y (+ folded W transpose) ----------------
// grid (100, 5): tile 0..3 = 25 Y rows each (2 thread-groups of 128: 13+12 rows,
// sharing W_cat lines via L1); tile 4 = W_num/b_num transpose.
__global__ __launch_bounds__(256) void precompute_Y(
    const float* __restrict__ emb_table,
    const float* __restrict__ gn_w, const float* __restrict__ gn_b,
    const float* __restrict__ W_cat, const float* __restrict__ b_cat,
    const float* __restrict__ W_num, const float* __restrict__ b_num)
{
    __shared__ __align__(16) float Esh[26 * 132];   // row 25 = scratch for group-1 overrun
    __shared__ float s_mean[25], s_rstd[25];

    const int g    = blockIdx.x;
    const int tile = blockIdx.y;
    const int tid  = threadIdx.x;

    if (tile == 4) {
        if (tid < 128) {
            int idx = g * 128 + tid;
            int o = idx / 100;
            int i = idx - o * 100;
            d_WnumT[idx] = W_num[i * 128 + o];
            d_bnumT[idx] = b_num[i * 128 + o];
        }
        return;
    }

    const int row0 = tile * 25;
    const int c    = tid & 127;     // o / column
    const int rg   = tid >> 7;      // 0 or 1

    // Load 25 raw embedding rows (rows rg, rg+2, ...)
    for (int r = rg; r < 25; r += 2)
        Esh[r * 132 + c] = emb_table[((size_t)(g * 100 + row0 + r)) * 128 + c];
    if (tid == 0) Esh[25 * 132] = 0.f;   // keep phantom row defined-ish (never stored)
    __syncthreads();

    if (tid < 25) {
        float s = 0.f, s2 = 0.f;
        #pragma unroll 8
        for (int k = 0; k < 128; ++k) {
            float v = Esh[tid * 132 + k];
            s += v; s2 += v * v;
        }
        float m   = s  * 0.0078125f;
        float var = fmaxf(s2 * 0.0078125f - m * m, 0.f);
        s_mean[tid] = m;
        s_rstd[tid] = rsqrtf(var + EPSF);
    }
    __syncthreads();

    const float gw = gn_w[g * 128 + c];
    const float gb = gn_b[g * 128 + c];
    for (int r = rg; r < 25; r += 2)
        Esh[r * 132 + c] = fmaf((Esh[r * 132 + c] - s_mean[r]) * s_rstd[r], gw, gb);
    __syncthreads();

    // Matmul: group 0 -> rows 0..12, group 1 -> rows 13..24 (13th is phantom)
    const int er0 = rg * 13;
    float acc[13];
    const float bc = b_cat[g * 128 + c];
    #pragma unroll
    for (int r = 0; r < 13; ++r) acc[r] = bc;

    const float* Wg = W_cat + (size_t)g * 16384 + c;
    #pragma unroll 2
    for (int k4 = 0; k4 < 32; ++k4) {
        float w0 = Wg[(k4 * 4 + 0) * 128];
        float w1 = Wg[(k4 * 4 + 1) * 128];
        float w2 = Wg[(k4 * 4 + 2) * 128];
        float w3 = Wg[(k4 * 4 + 3) * 128];
        #pragma unroll
        for (int r = 0; r < 13; ++r) {
            float4 e = *reinterpret_cast<const float4*>(&Esh[(er0 + r) * 132 + k4 * 4]);
            acc[r] = fmaf(e.x, w0, acc[r]);
            acc[r] = fmaf(e.y, w1, acc[r]);
            acc[r] = fmaf(e.z, w2, acc[r]);
            acc[r] = fmaf(e.w, w3, acc[r]);
        }
    }
    const int nr = rg ? 12 : 13;
    #pragma unroll
    for (int r = 0; r < 13; ++r)
        if (r < nr)
            d_Y[((size_t)(g * 100 + row0 + er0 + r)) * 128 + c] = sigf(acc[r]);
}

// ---------------- Kernel 2: fused gather + num branch ----------------
// grid (1024 quads, 4 cond-quarters), 512 threads.
// Phase A: gather (one 128B line per Y-row quarter) -> swizzled staging.
// Phase BC (unified): flat float4 index over the CONTIGUOUS 25.6KB per-sample
// output span -> perfectly coalesced 512B/warp STG. Per lane: f<25 computes
// the num branch (W/b hit L1 on sample revisits); f>=25 reads staged cat.
__global__ __launch_bounds__(512, 3) void fuse_main(
    const float* __restrict__ x_num, const int* __restrict__ x_cat,
    float* __restrict__ out)
{
    extern __shared__ __align__(16) float sh[];   // [4][32][128] = 64 KB
    __shared__ int   s_cat[400];
    __shared__ float s_num[400];

    const int tid  = threadIdx.x;
    const int w    = tid >> 5;
    const int lane = tid & 31;
    const int jj   = lane & 7;     // 16B chunk within 128B line (o-quad 0..7)
    const int sub  = lane >> 3;    // row within quad
    const int b0   = blockIdx.x * 4;
    const int ob   = blockIdx.y * 32;

    if (tid < 400) {
        s_cat[tid] = x_cat[b0 * 100 + tid];
        s_num[tid] = x_num[b0 * 100 + tid];
    }
    __syncthreads();

    // ---- Phase A: gather Y row-quarters -> swizzled transposed staging ----
    for (int it = w; it < 100; it += 16) {
        int s  = it / 25;
        int rq = it - s * 25;
        int r  = rq * 4 + sub;             // g row 0..99
        int cat = s_cat[s * 100 + r];
        float4 v = *reinterpret_cast<const float4*>(
            &d_Y[(r * 100 + cat) * 128 + ob + jj * 4]);
        int col = r ^ (jj * 4);
        float* dst = &sh[s * 4096 + (jj * 4) * 128 + col];
        dst[0 * 128] = v.x;
        dst[1 * 128] = v.y;
        dst[2 * 128] = v.z;
        dst[3 * 128] = v.w;
    }
    __syncthreads();

    // ---- Phase BC: unified, fully-coalesced output write ----
    // items: 4 samples x 32 o x 50 float4 = 6400; flat -> contiguous STG.
    for (int idx = tid; idx < 6400; idx += 512) {
        int s   = idx / 1600;
        int rem = idx - s * 1600;
        int o   = rem / 50;
        int f   = rem - o * 50;
        float4 v;
        if (f < 25) {   // numerical branch
            float4 ww = *reinterpret_cast<const float4*>(&d_WnumT[(ob + o) * 100 + f * 4]);
            float4 bb = *reinterpret_cast<const float4*>(&d_bnumT[(ob + o) * 100 + f * 4]);
            float4 xs = *reinterpret_cast<const float4*>(&s_num[s * 100 + f * 4]);
            v.x = sig_tanh(fmaf(xs.x, ww.x, bb.x));
            v.y = sig_tanh(fmaf(xs.y, ww.y, bb.y));
            v.z = sig_tanh(fmaf(xs.z, ww.z, bb.z));
            v.w = sig_tanh(fmaf(xs.w, ww.w, bb.w));
        } else {        // categorical branch from staging
            int g4 = f - 25;
            int colb = (g4 * 4) ^ (o & 28);
            v = *reinterpret_cast<const float4*>(&sh[s * 4096 + o * 128 + colb]);
        }
        *reinterpret_cast<float4*>(
            &out[(size_t)(b0 + s) * 25600 + (size_t)(ob + o) * 200 + f * 4]) = v;
    }
}

extern "C" void kernel_launch(void* const* d_in, const int* in_sizes, int n_in,
                              void* d_out, int out_size) {
    const float* x_num = (const float*)d_in[0];
    const int*   x_cat = (const int*)  d_in[1];
    const float* W_num = (const float*)d_in[2];
    const float* b_num = (const float*)d_in[3];
    const float* emb   = (const float*)d_in[4];
    const float* gn_w  = (const float*)d_in[5];
    const float* gn_b  = (const float*)d_in[6];
    const float* W_cat = (const float*)d_in[7];
    const float* b_cat = (const float*)d_in[8];
    float* out = (float*)d_out;

    const int smem_main = 4 * 32 * 128 * 4;   // 65536 B
    cudaFuncSetAttribute(fuse_main, cudaFuncAttributeMaxDynamicSharedMemorySize, smem_main);

    precompute_Y<<<dim3(100, 5), 256>>>(emb, gn_w, gn_b, W_cat, b_cat, W_num, b_num);
    fuse_main<<<dim3(1024, 4), 512, smem_main>>>(x_num, x_cat, out);
}

// round 14
// speedup vs baseline: 1.0761x; 1.0761x over previous
#include <cuda_runtime.h>

#define EPSF 1e-5f

// Precomputed categorical results: Y[g][cat][o] = sigmoid(GN(emb[g*100+cat]) @ W_cat[g] + b_cat[g])
__device__ __align__(16) float d_Y[100 * 100 * 128];
// Transposed num weights: WnumT[o][i] = W_num[i][o]  (128 x 100)
__device__ __align__(16) float d_WnumT[128 * 100];
__device__ __align__(16) float d_bnumT[128 * 100];

__device__ __forceinline__ float sigf(float x) { return 1.0f / (1.0f + __expf(-x)); }

__device__ __forceinline__ float sig_tanh(float x) {
    // sigmoid(x) = 0.5*tanh(0.5x) + 0.5 ; MUFU.TANH
    float t;
    asm("tanh.approx.f32 %0, %1;" : "=f"(t) : "f"(0.5f * x));
    return fmaf(0.5f, t, 0.5f);
}

// ---- f32x2 packed-FMA helpers (FFMA2: sm_103a, PTX-only) ----
__device__ __forceinline__ unsigned long long pack2(float lo, float hi) {
    unsigned long long r;
    asm("mov.b64 %0, {%1, %2};" : "=l"(r) : "f"(lo), "f"(hi));
    return r;
}
__device__ __forceinline__ unsigned long long fma2(
    unsigned long long a, unsigned long long b, unsigned long long c) {
    unsigned long long d;
    asm("fma.rn.f32x2 %0, %1, %2, %3;" : "=l"(d) : "l"(a), "l"(b), "l"(c));
    return d;
}
__device__ __forceinline__ float2 unpack2(unsigned long long v) {
    float2 f;
    asm("mov.b64 {%0, %1}, %2;" : "=f"(f.x), "=f"(f.y) : "l"(v));
    return f;
}

// ---------------- Kernel 1: precompute Y (+ folded W transpose) ----------------
// grid (100, 6): tile 0..4 = 20 Y rows each via FFMA2 (row pairs packed in
// f32x2 lanes); tile 5 = W_num/b_num transpose.
// Esh is k-major [k][row] so row-pairs load directly as b64 (lane-broadcast).
__global__ __launch_bounds__(128) void precompute_Y(
    const float* __restrict__ emb_table,
    const float* __restrict__ gn_w, const float* __restrict__ gn_b,
    const float* __restrict__ W_cat, const float* __restrict__ b_cat,
    const float* __restrict__ W_num, const float* __restrict__ b_num)
{
    __shared__ __align__(16) float Esh[128 * 20];   // [k][row]
    __shared__ float s_mean[20], s_rstd[20];

    const int g    = blockIdx.x;
    const int tile = blockIdx.y;
    const int tid  = threadIdx.x;      // = column k for loads, = output o for matmul

    if (tile == 5) {
        int idx = g * 128 + tid;
        int o = idx / 100;
        int i = idx - o * 100;
        d_WnumT[idx] = W_num[i * 128 + o];
        d_bnumT[idx] = b_num[i * 128 + o];
        return;
    }

    const int row0 = tile * 20;

    // Load 20 rows transposed: thread tid = col k (coalesced LDG per row)
    #pragma unroll 5
    for (int r = 0; r < 20; ++r)
        Esh[tid * 20 + r] = emb_table[((size_t)(g * 100 + row0 + r)) * 128 + tid];
    __syncthreads();

    // Per-row mean/rstd (threads 0..19; lanes hit distinct banks per k)
    if (tid < 20) {
        float s = 0.f, s2 = 0.f;
        #pragma unroll 8
        for (int k = 0; k < 128; ++k) {
            float v = Esh[k * 20 + tid];
            s += v; s2 += v * v;
        }
        float m   = s  * 0.0078125f;
        float var = fmaxf(s2 * 0.0078125f - m * m, 0.f);
        s_mean[tid] = m;
        s_rstd[tid] = rsqrtf(var + EPSF);
    }
    __syncthreads();

    // Normalize + affine (gn indexed by cond k = tid)
    const float gw = gn_w[g * 128 + tid];
    const float gb = gn_b[g * 128 + tid];
    #pragma unroll 5
    for (int r = 0; r < 20; ++r)
        Esh[tid * 20 + r] = fmaf((Esh[tid * 20 + r] - s_mean[r]) * s_rstd[r], gw, gb);
    __syncthreads();

    // Matmul: thread = output column o (=tid); 10 f32x2 accumulators = 20 rows.
    const float bc = b_cat[g * 128 + tid];
    unsigned long long acc[10];
    const unsigned long long bc2 = pack2(bc, bc);
    #pragma unroll
    for (int p = 0; p < 10; ++p) acc[p] = bc2;

    const float* Wg = W_cat + (size_t)g * 16384 + tid;
    #pragma unroll 4
    for (int k = 0; k < 128; ++k) {
        float w = Wg[k * 128];                       // coalesced scalar LDG
        unsigned long long w2 = pack2(w, w);
        const unsigned long long* e2 =
            reinterpret_cast<const unsigned long long*>(&Esh[k * 20]);  // broadcast
        #pragma unroll
        for (int p = 0; p < 10; ++p)
            acc[p] = fma2(e2[p], w2, acc[p]);
    }

    #pragma unroll
    for (int p = 0; p < 10; ++p) {
        float2 v = unpack2(acc[p]);
        d_Y[((size_t)(g * 100 + row0 + 2 * p + 0)) * 128 + tid] = sigf(v.x);
        d_Y[((size_t)(g * 100 + row0 + 2 * p + 1)) * 128 + tid] = sigf(v.y);
    }
}

// ---------------- Kernel 2: fused gather + num branch (exact R12 winner) ----------------
// grid (1024 quads, 4 cond-quarters), 512 threads.
// Block = 4 samples x 32-cond quarter:
//  - gather: each Y-row quarter = exactly one 128B line (8 lanes x 16B)
//  - W/b read once per block, reused by 4 samples (quarter-sized)
//  - staging [4][32][128] with XOR swizzle col = g ^ (4*jj): STS banks
//    sub x (rq^jj) all distinct; LDS.128 16B-aligned, phase-bijective.
__global__ __launch_bounds__(512, 3) void fuse_main(
    const float* __restrict__ x_num, const int* __restrict__ x_cat,
    float* __restrict__ out)
{
    extern __shared__ __align__(16) float sh[];   // [4][32][128] = 64 KB
    __shared__ int   s_cat[400];
    __shared__ float s_num[400];

    const int tid  = threadIdx.x;
    const int w    = tid >> 5;
    const int lane = tid & 31;
    const int jj   = lane & 7;     // 16B chunk within 128B line (o-quad 0..7)
    const int sub  = lane >> 3;    // row within quad
    const int b0   = blockIdx.x * 4;
    const int ob   = blockIdx.y * 32;

    if (tid < 400) {
        s_cat[tid] = x_cat[b0 * 100 + tid];
        s_num[tid] = x_num[b0 * 100 + tid];
    }
    __syncthreads();

    // ---- Phase A: gather Y row-quarters -> swizzled transposed staging ----
    // work item: (s, rq): 4 samples x 25 row-quads = 100 warp-iters
    for (int it = w; it < 100; it += 16) {
        int s  = it / 25;
        int rq = it - s * 25;
        int r  = rq * 4 + sub;             // g row 0..99
        int cat = s_cat[s * 100 + r];
        float4 v = *reinterpret_cast<const float4*>(
            &d_Y[(r * 100 + cat) * 128 + ob + jj * 4]);
        int col = r ^ (jj * 4);
        float* dst = &sh[s * 4096 + (jj * 4) * 128 + col];
        dst[0 * 128] = v.x;
        dst[1 * 128] = v.y;
        dst[2 * 128] = v.z;
        dst[3 * 128] = v.w;
    }

    // ---- Phase B: num branch, W/b loaded once, reused for 4 samples ----
    #pragma unroll 2
    for (int idx = tid; idx < 800; idx += 512) {
        int o  = idx / 25;
        int i4 = idx - o * 25;
        float4 ww = *reinterpret_cast<const float4*>(&d_WnumT[(ob + o) * 100 + i4 * 4]);
        float4 bb = *reinterpret_cast<const float4*>(&d_bnumT[(ob + o) * 100 + i4 * 4]);
        #pragma unroll
        for (int s = 0; s < 4; ++s) {
            float4 xs = *reinterpret_cast<const float4*>(&s_num[s * 100 + i4 * 4]);
            float4 r;
            r.x = sig_tanh(fmaf(xs.x, ww.x, bb.x));
            r.y = sig_tanh(fmaf(xs.y, ww.y, bb.y));
            r.z = sig_tanh(fmaf(xs.z, ww.z, bb.z));
            r.w = sig_tanh(fmaf(xs.w, ww.w, bb.w));
            *reinterpret_cast<float4*>(
                &out[(size_t)(b0 + s) * 25600 + (size_t)(ob + o) * 200 + i4 * 4]) = r;
        }
    }
    __syncthreads();

    // ---- Phase C: cat output, swizzled LDS.128 + coalesced STG.128 ----
    #pragma unroll 2
    for (int idx = tid; idx < 3200; idx += 512) {
        int s   = idx / 800;
        int rem = idx - s * 800;
        int o   = rem / 25;
        int g4  = rem - o * 25;
        int colb = (g4 * 4) ^ (o & 28);
        float4 v = *reinterpret_cast<const float4*>(&sh[s * 4096 + o * 128 + colb]);
        *reinterpret_cast<float4*>(
            &out[(size_t)(b0 + s) * 25600 + (size_t)(ob + o) * 200 + 100 + g4 * 4]) = v;
    }
}

extern "C" void kernel_launch(void* const* d_in, const int* in_sizes, int n_in,
                              void* d_out, int out_size) {
    const float* x_num = (const float*)d_in[0];
    const int*   x_cat = (const int*)  d_in[1];
    const float* W_num = (const float*)d_in[2];
    const float* b_num = (const float*)d_in[3];
    const float* emb   = (const float*)d_in[4];
    const float* gn_w  = (const float*)d_in[5];
    const float* gn_b  = (const float*)d_in[6];
    const float* W_cat = (const float*)d_in[7];
    const float* b_cat = (const float*)d_in[8];
    float* out = (float*)d_out;

    const int smem_main = 4 * 32 * 128 * 4;   // 65536 B
    cudaFuncSetAttribute(fuse_main, cudaFuncAttributeMaxDynamicSharedMemorySize, smem_main);

    precompute_Y<<<dim3(100, 6), 128>>>(emb, gn_w, gn_b, W_cat, b_cat, W_num, b_num);
    fuse_main<<<dim3(1024, 4), 512, smem_main>>>(x_num, x_cat, out);
}

// round 16
// speedup vs baseline: 1.1237x; 1.0442x over previous
#include <cuda_runtime.h>

#define EPSF 1e-5f

// Precomputed categorical results: Y[g][cat][o] = sigmoid(GN(emb[g*100+cat]) @ W_cat[g] + b_cat[g])
__device__ __align__(16) float d_Y[100 * 100 * 128];
// Transposed num weights: WnumT[o][i] = W_num[i][o]  (128 x 100)
__device__ __align__(16) float d_WnumT[128 * 100];
__device__ __align__(16) float d_bnumT[128 * 100];

__device__ __forceinline__ float sigf(float x) { return 1.0f / (1.0f + __expf(-x)); }

__device__ __forceinline__ float sig_tanh(float x) {
    // sigmoid(x) = 0.5*tanh(0.5x) + 0.5 ; MUFU.TANH
    float t;
    asm("tanh.approx.f32 %0, %1;" : "=f"(t) : "f"(0.5f * x));
    return fmaf(0.5f, t, 0.5f);
}

// ---------------- Kernel 0: transpose W_num/b_num (strictly first) ----------------
__global__ __launch_bounds__(256) void transpose_wb(
    const float* __restrict__ W_num, const float* __restrict__ b_num)
{
    int idx = blockIdx.x * 256 + threadIdx.x;
    if (idx < 12800) {
        int o = idx / 100;
        int i = idx - o * 100;
        d_WnumT[idx] = W_num[i * 128 + o];
        d_bnumT[idx] = b_num[i * 128 + o];
    }
}

// ---------------- Kernel 1: precompute Y (R12 10-row tiles; PDL primary) ----------------
__global__ __launch_bounds__(128) void precompute_Y(
    const float* __restrict__ emb_table,
    const float* __restrict__ gn_w, const float* __restrict__ gn_b,
    const float* __restrict__ W_cat, const float* __restrict__ b_cat)
{
    // Let the dependent fuse_main launch immediately (its pre-sync phase only
    // touches k0 outputs + fresh inputs; d_Y reads are behind griddepsync).
    cudaTriggerProgrammaticLaunchCompletion();

    __shared__ __align__(16) float Esh[10 * 132];
    __shared__ float s_mean[10], s_rstd[10];

    const int g    = blockIdx.x;
    const int tile = blockIdx.y;
    const int tid  = threadIdx.x;

    const int row0 = tile * 10;
    #pragma unroll
    for (int r = 0; r < 10; ++r)
        Esh[r * 132 + tid] = emb_table[((size_t)(g * 100 + row0 + r)) * 128 + tid];
    __syncthreads();

    if (tid < 10) {
        float s = 0.f, s2 = 0.f;
        #pragma unroll 8
        for (int k = 0; k < 128; ++k) {
            float v = Esh[tid * 132 + k];
            s += v; s2 += v * v;
        }
        float m   = s  * 0.0078125f;
        float var = fmaxf(s2 * 0.0078125f - m * m, 0.f);
        s_mean[tid] = m;
        s_rstd[tid] = rsqrtf(var + EPSF);
    }
    __syncthreads();

    const float gw = gn_w[g * 128 + tid];
    const float gb = gn_b[g * 128 + tid];
    #pragma unroll
    for (int r = 0; r < 10; ++r)
        Esh[r * 132 + tid] = fmaf((Esh[r * 132 + tid] - s_mean[r]) * s_rstd[r], gw, gb);
    __syncthreads();

    float acc[10];
    const float bc = b_cat[g * 128 + tid];
    #pragma unroll
    for (int r = 0; r < 10; ++r) acc[r] = bc;

    const float* Wg = W_cat + (size_t)g * 16384 + tid;
    #pragma unroll 4
    for (int k4 = 0; k4 < 32; ++k4) {
        float w0 = Wg[(k4 * 4 + 0) * 128];
        float w1 = Wg[(k4 * 4 + 1) * 128];
        float w2 = Wg[(k4 * 4 + 2) * 128];
        float w3 = Wg[(k4 * 4 + 3) * 128];
        #pragma unroll
        for (int r = 0; r < 10; ++r) {
            float4 e = *reinterpret_cast<const float4*>(&Esh[r * 132 + k4 * 4]);
            acc[r] = fmaf(e.x, w0, acc[r]);
            acc[r] = fmaf(e.y, w1, acc[r]);
            acc[r] = fmaf(e.z, w2, acc[r]);
            acc[r] = fmaf(e.w, w3, acc[r]);
        }
    }
    #pragma unroll
    for (int r = 0; r < 10; ++r)
        d_Y[((size_t)(g * 100 + row0 + r)) * 128 + tid] = sigf(acc[r]);
}

// ---------------- Kernel 2: fused gather + num branch (PDL secondary) ----------------
// grid (1024 quads, 4 cond-quarters), 512 threads.
// Order: Phase B (num; independent of precompute_Y) -> griddepsync -> gather.
// Block = 4 samples x 32-cond quarter:
//  - gather: each Y-row quarter = exactly one 128B line (8 lanes x 16B)
//  - W/b read once per block, reused by 4 samples
//  - staging [4][32][128] with XOR swizzle col = g ^ (4*jj)
__global__ __launch_bounds__(512, 3) void fuse_main(
    const float* __restrict__ x_num, const int* __restrict__ x_cat,
    float* __restrict__ out)
{
    extern __shared__ __align__(16) float sh[];   // [4][32][128] = 64 KB
    __shared__ int   s_cat[400];
    __shared__ float s_num[400];

    const int tid  = threadIdx.x;
    const int w    = tid >> 5;
    const int lane = tid & 31;
    const int jj   = lane & 7;     // 16B chunk within 128B line (o-quad 0..7)
    const int sub  = lane >> 3;    // row within quad
    const int b0   = blockIdx.x * 4;
    const int ob   = blockIdx.y * 32;

    if (tid < 400) {
        s_cat[tid] = x_cat[b0 * 100 + tid];
        s_num[tid] = x_num[b0 * 100 + tid];
    }
    __syncthreads();

    // ---- Phase B: num branch (independent of precompute_Y; overlaps it) ----
    #pragma unroll 2
    for (int idx = tid; idx < 800; idx += 512) {
        int o  = idx / 25;
        int i4 = idx - o * 25;
        float4 ww = *reinterpret_cast<const float4*>(&d_WnumT[(ob + o) * 100 + i4 * 4]);
        float4 bb = *reinterpret_cast<const float4*>(&d_bnumT[(ob + o) * 100 + i4 * 4]);
        #pragma unroll
        for (int s = 0; s < 4; ++s) {
            float4 xs = *reinterpret_cast<const float4*>(&s_num[s * 100 + i4 * 4]);
            float4 r;
            r.x = sig_tanh(fmaf(xs.x, ww.x, bb.x));
            r.y = sig_tanh(fmaf(xs.y, ww.y, bb.y));
            r.z = sig_tanh(fmaf(xs.z, ww.z, bb.z));
            r.w = sig_tanh(fmaf(xs.w, ww.w, bb.w));
            *reinterpret_cast<float4*>(
                &out[(size_t)(b0 + s) * 25600 + (size_t)(ob + o) * 200 + i4 * 4]) = r;
        }
    }

    // Wait for precompute_Y's d_Y to be complete & visible.
    cudaGridDependencySynchronize();

    // ---- Phase A: gather Y row-quarters -> swizzled transposed staging ----
    for (int it = w; it < 100; it += 16) {
        int s  = it / 25;
        int rq = it - s * 25;
        int r  = rq * 4 + sub;             // g row 0..99
        int cat = s_cat[s * 100 + r];
        float4 v = *reinterpret_cast<const float4*>(
            &d_Y[(r * 100 + cat) * 128 + ob + jj * 4]);
        int col = r ^ (jj * 4);
        float* dst = &sh[s * 4096 + (jj * 4) * 128 + col];
        dst[0 * 128] = v.x;
        dst[1 * 128] = v.y;
        dst[2 * 128] = v.z;
        dst[3 * 128] = v.w;
    }
    __syncthreads();

    // ---- Phase C: cat output, swizzled LDS.128 + coalesced STG.128 ----
    #pragma unroll 2
    for (int idx = tid; idx < 3200; idx += 512) {
        int s   = idx / 800;
        int rem = idx - s * 800;
        int o   = rem / 25;
        int g4  = rem - o * 25;
        int colb = (g4 * 4) ^ (o & 28);
        float4 v = *reinterpret_cast<const float4*>(&sh[s * 4096 + o * 128 + colb]);
        *reinterpret_cast<float4*>(
            &out[(size_t)(b0 + s) * 25600 + (size_t)(ob + o) * 200 + 100 + g4 * 4]) = v;
    }
}

extern "C" void kernel_launch(void* const* d_in, const int* in_sizes, int n_in,
                              void* d_out, int out_size) {
    const float* x_num = (const float*)d_in[0];
    const int*   x_cat = (const int*)  d_in[1];
    const float* W_num = (const float*)d_in[2];
    const float* b_num = (const float*)d_in[3];
    const float* emb   = (const float*)d_in[4];
    const float* gn_w  = (const float*)d_in[5];
    const float* gn_b  = (const float*)d_in[6];
    const float* W_cat = (const float*)d_in[7];
    const float* b_cat = (const float*)d_in[8];
    float* out = (float*)d_out;

    const int smem_main = 4 * 32 * 128 * 4;   // 65536 B
    cudaFuncSetAttribute(fuse_main, cudaFuncAttributeMaxDynamicSharedMemorySize, smem_main);

    transpose_wb<<<50, 256>>>(W_num, b_num);
    precompute_Y<<<dim3(100, 10), 128>>>(emb, gn_w, gn_b, W_cat, b_cat);

    // fuse_main as PDL secondary: launches during precompute_Y; Phase B runs
    // pre-sync, gather phases after cudaGridDependencySynchronize().
    cudaLaunchConfig_t cfg = {};
    cfg.gridDim  = dim3(1024, 4, 1);
    cfg.blockDim = dim3(512, 1, 1);
    cfg.dynamicSmemBytes = smem_main;
    cfg.stream = 0;
    cudaLaunchAttribute attrs[1];
    attrs[0].id = cudaLaunchAttributeProgrammaticStreamSerialization;
    attrs[0].val.programmaticStreamSerializationAllowed = 1;
    cfg.attrs = attrs;
    cfg.numAttrs = 1;
    cudaLaunchKernelEx(&cfg, fuse_main, x_num, x_cat, out);
}

// round 17
// speedup vs baseline: 1.1622x; 1.0343x over previous
#include <cuda_runtime.h>

#define EPSF 1e-5f

// Precomputed categorical results: Y[g][cat][o] = sigmoid(GN(emb[g*100+cat]) @ W_cat[g] + b_cat[g])
__device__ __align__(16) float d_Y[100 * 100 * 128];
// Transposed num weights: WnumT[o][i] = W_num[i][o]  (128 x 100)
__device__ __align__(16) float d_WnumT[128 * 100];
__device__ __align__(16) float d_bnumT[128 * 100];

__device__ __forceinline__ float sigf(float x) { return 1.0f / (1.0f + __expf(-x)); }

__device__ __forceinline__ float sig_tanh(float x) {
    // sigmoid(x) = 0.5*tanh(0.5x) + 0.5 ; MUFU.TANH
    float t;
    asm("tanh.approx.f32 %0, %1;" : "=f"(t) : "f"(0.5f * x));
    return fmaf(0.5f, t, 0.5f);
}

// ---------------- Kernel 1: precompute Y (+ folded W transpose) ----------------
// grid (100, 6): tile 0..4 = 20 Y rows each; tile 5 = W_num/b_num transpose.
// 20-row tiles: W_cat read 5x (32 MB L2, was 64 MB at 10-row) while keeping
// 500 blocks (3.4/SM) with 80 independent FMAs per 4-load group to hide LDG.
__global__ __launch_bounds__(128) void precompute_Y(
    const float* __restrict__ emb_table,
    const float* __restrict__ gn_w, const float* __restrict__ gn_b,
    const float* __restrict__ W_cat, const float* __restrict__ b_cat,
    const float* __restrict__ W_num, const float* __restrict__ b_num)
{
    __shared__ __align__(16) float Esh[20 * 132];
    __shared__ float s_mean[20], s_rstd[20];

    const int g    = blockIdx.x;
    const int tile = blockIdx.y;
    const int tid  = threadIdx.x;

    if (tile == 5) {
        int idx = g * 128 + tid;
        int o = idx / 100;
        int i = idx - o * 100;
        d_WnumT[idx] = W_num[i * 128 + o];
        d_bnumT[idx] = b_num[i * 128 + o];
        return;
    }

    const int row0 = tile * 20;
    #pragma unroll
    for (int r = 0; r < 20; ++r)
        Esh[r * 132 + tid] = emb_table[((size_t)(g * 100 + row0 + r)) * 128 + tid];
    __syncthreads();

    if (tid < 20) {
        float s = 0.f, s2 = 0.f;
        #pragma unroll 8
        for (int k = 0; k < 128; ++k) {
            float v = Esh[tid * 132 + k];
            s += v; s2 += v * v;
        }
        float m   = s  * 0.0078125f;
        float var = fmaxf(s2 * 0.0078125f - m * m, 0.f);
        s_mean[tid] = m;
        s_rstd[tid] = rsqrtf(var + EPSF);
    }
    __syncthreads();

    const float gw = gn_w[g * 128 + tid];
    const float gb = gn_b[g * 128 + tid];
    #pragma unroll
    for (int r = 0; r < 20; ++r)
        Esh[r * 132 + tid] = fmaf((Esh[r * 132 + tid] - s_mean[r]) * s_rstd[r], gw, gb);
    __syncthreads();

    float acc[20];
    const float bc = b_cat[g * 128 + tid];
    #pragma unroll
    for (int r = 0; r < 20; ++r) acc[r] = bc;

    const float* Wg = W_cat + (size_t)g * 16384 + tid;
    #pragma unroll 2
    for (int k4 = 0; k4 < 32; ++k4) {
        float w0 = Wg[(k4 * 4 + 0) * 128];
        float w1 = Wg[(k4 * 4 + 1) * 128];
        float w2 = Wg[(k4 * 4 + 2) * 128];
        float w3 = Wg[(k4 * 4 + 3) * 128];
        #pragma unroll
        for (int r = 0; r < 20; ++r) {
            float4 e = *reinterpret_cast<const float4*>(&Esh[r * 132 + k4 * 4]);
            acc[r] = fmaf(e.x, w0, acc[r]);
            acc[r] = fmaf(e.y, w1, acc[r]);
            acc[r] = fmaf(e.z, w2, acc[r]);
            acc[r] = fmaf(e.w, w3, acc[r]);
        }
    }
    #pragma unroll
    for (int r = 0; r < 20; ++r)
        d_Y[((size_t)(g * 100 + row0 + r)) * 128 + tid] = sigf(acc[r]);
}

// ---------------- Kernel 2: fused gather + num branch (exact R12 winner) ----------------
// grid (1024 quads, 4 cond-quarters), 512 threads.
// Block = 4 samples x 32-cond quarter:
//  - gather: each Y-row quarter = exactly one 128B line (8 lanes x 16B)
//  - W/b read once per block, reused by 4 samples (quarter-sized)
//  - staging [4][32][128] with XOR swizzle col = g ^ (4*jj): STS banks
//    sub x (rq^jj) all distinct; LDS.128 16B-aligned, phase-bijective.
__global__ __launch_bounds__(512, 3) void fuse_main(
    const float* __restrict__ x_num, const int* __restrict__ x_cat,
    float* __restrict__ out)
{
    extern __shared__ __align__(16) float sh[];   // [4][32][128] = 64 KB
    __shared__ int   s_cat[400];
    __shared__ float s_num[400];

    const int tid  = threadIdx.x;
    const int w    = tid >> 5;
    const int lane = tid & 31;
    const int jj   = lane & 7;     // 16B chunk within 128B line (o-quad 0..7)
    const int sub  = lane >> 3;    // row within quad
    const int b0   = blockIdx.x * 4;
    const int ob   = blockIdx.y * 32;

    if (tid < 400) {
        s_cat[tid] = x_cat[b0 * 100 + tid];
        s_num[tid] = x_num[b0 * 100 + tid];
    }
    __syncthreads();

    // ---- Phase A: gather Y row-quarters -> swizzled transposed staging ----
    // work item: (s, rq): 4 samples x 25 row-quads = 100 warp-iters
    for (int it = w; it < 100; it += 16) {
        int s  = it / 25;
        int rq = it - s * 25;
        int r  = rq * 4 + sub;             // g row 0..99
        int cat = s_cat[s * 100 + r];
        float4 v = *reinterpret_cast<const float4*>(
            &d_Y[(r * 100 + cat) * 128 + ob + jj * 4]);
        int col = r ^ (jj * 4);
        float* dst = &sh[s * 4096 + (jj * 4) * 128 + col];
        dst[0 * 128] = v.x;
        dst[1 * 128] = v.y;
        dst[2 * 128] = v.z;
        dst[3 * 128] = v.w;
    }

    // ---- Phase B: num branch, W/b loaded once, reused for 4 samples ----
    #pragma unroll 2
    for (int idx = tid; idx < 800; idx += 512) {
        int o  = idx / 25;
        int i4 = idx - o * 25;
        float4 ww = *reinterpret_cast<const float4*>(&d_WnumT[(ob + o) * 100 + i4 * 4]);
        float4 bb = *reinterpret_cast<const float4*>(&d_bnumT[(ob + o) * 100 + i4 * 4]);
        #pragma unroll
        for (int s = 0; s < 4; ++s) {
            float4 xs = *reinterpret_cast<const float4*>(&s_num[s * 100 + i4 * 4]);
            float4 r;
            r.x = sig_tanh(fmaf(xs.x, ww.x, bb.x));
            r.y = sig_tanh(fmaf(xs.y, ww.y, bb.y));
            r.z = sig_tanh(fmaf(xs.z, ww.z, bb.z));
            r.w = sig_tanh(fmaf(xs.w, ww.w, bb.w));
            *reinterpret_cast<float4*>(
                &out[(size_t)(b0 + s) * 25600 + (size_t)(ob + o) * 200 + i4 * 4]) = r;
        }
    }
    __syncthreads();

    // ---- Phase C: cat output, swizzled LDS.128 + coalesced STG.128 ----
    #pragma unroll 2
    for (int idx = tid; idx < 3200; idx += 512) {
        int s   = idx / 800;
        int rem = idx - s * 800;
        int o   = rem / 25;
        int g4  = rem - o * 25;
        int colb = (g4 * 4) ^ (o & 28);
        float4 v = *reinterpret_cast<const float4*>(&sh[s * 4096 + o * 128 + colb]);
        *reinterpret_cast<float4*>(
            &out[(size_t)(b0 + s) * 25600 + (size_t)(ob + o) * 200 + 100 + g4 * 4]) = v;
    }
}

extern "C" void kernel_launch(void* const* d_in, const int* in_sizes, int n_in,
                              void* d_out, int out_size) {
    const float* x_num = (const float*)d_in[0];
    const int*   x_cat = (const int*)  d_in[1];
    const float* W_num = (const float*)d_in[2];
    const float* b_num = (const float*)d_in[3];
    const float* emb   = (const float*)d_in[4];
    const float* gn_w  = (const float*)d_in[5];
    const float* gn_b  = (const float*)d_in[6];
    const float* W_cat = (const float*)d_in[7];
    const float* b_cat = (const float*)d_in[8];
    float* out = (float*)d_out;

    const int smem_main = 4 * 32 * 128 * 4;   // 65536 B
    cudaFuncSetAttribute(fuse_main, cudaFuncAttributeMaxDynamicSharedMemorySize, smem_main);

    precompute_Y<<<dim3(100, 6), 128>>>(emb, gn_w, gn_b, W_cat, b_cat, W_num, b_num);
    fuse_main<<<dim3(1024, 4), 512, smem_main>>>(x_num, x_cat, out);
}